// round 14
// baseline (speedup 1.0000x reference)
#include <cuda_runtime.h>

// out = M rho M^T on the Hamming-weight-2 basis (N = C(32,2) = 496).
// M block-diagonal over 36 pair-blocks; TWO distinct 4x4 tile matrices
// (V_row: params 0-5, V_col: params 6-11), pyramid order {0,1,0,2,1,0}.
//   cross block (t1<t2): dim 16, B = V_t1 (x) V_t2
//   diag  block (t):     dim 6,  B = Lambda^2(V_t) = W
// SYMMETRY: compute only I <= J (666 CTAs), mirror out[J,I] = out[I,J]^T.
// Cross path lane map: thread = (col c = tid&15, row-quad rg = tid>>4),
// 4 quad rows in registers -> every LDG/STG instruction is 8-sector
// coalesced (2 rows x 4 contiguous runs). be-mix register-local, al-mix via
// shfl+1 smem exchange, de/ga-mix lane butterflies. Mirror via smem transpose.

#define NP 496
#define FM 0xFFFFFFFFu

__device__ __forceinline__ int pair_idx(int a, int b) {
    return a * 31 - (a * (a - 1)) / 2 + (b - a - 1);
}

__device__ __forceinline__ void decode_block(int B, int& t1, int& t2, int& dim) {
    if (B < 28) {
        int rem = B, a = 0;
        while (rem >= 7 - a) { rem -= 7 - a; a++; }
        t1 = a; t2 = a + 1 + rem; dim = 16;
    } else {
        t1 = B - 28; t2 = t1; dim = 6;
    }
}

__device__ __forceinline__ int tri_base(int I) { return (73 * I - I * I) >> 1; }

// P1 = {0,0,0,1,1,2}, P2 = {1,2,3,2,3,3}, 3 bits/entry
#define P1W 0x11200
#define P2W 0x1B4D1
__device__ __forceinline__ int p1of(int m) { return (P1W >> (3 * m)) & 7; }
__device__ __forceinline__ int p2of(int m) { return (P2W >> (3 * m)) & 7; }

template <int D>
__device__ __forceinline__ int gidx(int t1, int t2, int m) {
    if (D == 16) return pair_idx(4 * t1 + (m >> 2), 4 * t2 + (m & 3));
    return pair_idx(4 * t1 + p1of(m), 4 * t1 + p2of(m));
}

// One warp composes BOTH tile matrices: half-warp h builds group h.
// Lane h*16+idx ends holding V[h][idx]; written to warp-private sVw[32].
__device__ __forceinline__ void compose_V_warp(int lane, const float* __restrict__ thetas,
                                               float* sVw) {
    const int h = lane >> 4, idx = lane & 15;
    float s, c;
    sincosf(__ldg(thetas + h * 6 + (idx % 6)), &s, &c);
    const int r = idx >> 2;
    float v = ((idx >> 2) == (idx & 3)) ? 1.f : 0.f;
    const int jseq[6] = {0, 1, 0, 2, 1, 0};
    #pragma unroll
    for (int gi = 0; gi < 6; gi++) {
        const int j = jseq[gi];
        const int src = (lane & 16) + gi;
        float cg = __shfl_sync(FM, c, src);
        float sg = __shfl_sync(FM, s, src);
        float vu = __shfl_sync(FM, v, (lane + 4) & 31);
        float vd = __shfl_sync(FM, v, (lane - 4) & 31);
        if (r == j)          v = cg * v + sg * vu;
        else if (r == j + 1) v = cg * v - sg * vd;
    }
    sVw[lane] = v;
}

// ---- cross x cross (16x16) --------------------------------------------------
__device__ __forceinline__ void path_cross16(
    const float* __restrict__ rho, float* __restrict__ out,
    const float* __restrict__ thetas,
    int T1, int T2, int t1, int t2, int tid, bool mirror,
    float (*sVw)[32], float4* sY, float (*sT)[20])
{
    const int w = tid >> 5, lane = tid & 31;
    const int c  = tid & 15;     // block column 0..15 (lane bits 0-3)
    const int rg = tid >> 4;     // row quad 0..3 (lane bit 4 + warp)

    const int growb = pair_idx(4 * T1 + rg, 4 * T2);        // rows growb..+3
    const int gcol  = pair_idx(4 * t1 + (c >> 2), 4 * t2 + (c & 3));

    // coalesced gather: instr k -> 2 rows x 4 runs = 8 sectors per warp
    const float* pr = rho + growb * NP + gcol;
    float x0 = __ldg(pr);
    float x1 = __ldg(pr + NP);
    float x2 = __ldg(pr + 2 * NP);
    float x3 = __ldg(pr + 3 * NP);

    float* sV = sVw[w];
    compose_V_warp(lane, thetas, sV);      // overlaps the gather; warp-private
    __syncwarp();

    const float* V1 = sV + (T1 >> 2) * 16;
    const float* V2 = sV + (T2 >> 2) * 16;
    const float* U1 = sV + (t1 >> 2) * 16;
    const float* U2 = sV + (t2 >> 2) * 16;

    // LEFT stage 1: be-mix, register-local (row within quad = register index)
    float y0 = V2[0]  * x0 + V2[1]  * x1 + V2[2]  * x2 + V2[3]  * x3;
    float y1 = V2[4]  * x0 + V2[5]  * x1 + V2[6]  * x2 + V2[7]  * x3;
    float y2 = V2[8]  * x0 + V2[9]  * x1 + V2[10] * x2 + V2[11] * x3;
    float y3 = V2[12] * x0 + V2[13] * x1 + V2[14] * x2 + V2[15] * x3;

    // LEFT stage 2: al-mix (rg). rg^1 via shfl mask 16; rg^2, rg^3 via smem.
    float p0 = __shfl_xor_sync(FM, y0, 16);
    float p1 = __shfl_xor_sync(FM, y1, 16);
    float p2 = __shfl_xor_sync(FM, y2, 16);
    float p3 = __shfl_xor_sync(FM, y3, 16);
    sY[tid] = make_float4(y0, y1, y2, y3);
    __syncthreads();
    float4 q2 = sY[tid ^ 32];
    float4 q3 = sY[tid ^ 48];

    const float a0 = V1[rg * 4 + rg];
    const float a1 = V1[rg * 4 + (rg ^ 1)];
    const float a2 = V1[rg * 4 + (rg ^ 2)];
    const float a3 = V1[rg * 4 + (rg ^ 3)];
    float z0 = a0 * y0 + a1 * p0 + a2 * q2.x + a3 * q3.x;
    float z1 = a0 * y1 + a1 * p1 + a2 * q2.y + a3 * q3.y;
    float z2 = a0 * y2 + a1 * p2 + a2 * q2.z + a3 * q3.z;
    float z3 = a0 * y3 + a1 * p3 + a2 * q2.w + a3 * q3.w;

    // RIGHT stage A: de-mix (col bits 0,1 of lane) -> masks 1,2,3
    const int de = c & 3;
    const float d0 = U2[de * 4 + de];
    const float d1 = U2[de * 4 + (de ^ 1)];
    const float d2 = U2[de * 4 + (de ^ 2)];
    const float d3 = U2[de * 4 + (de ^ 3)];
    float w0 = d0 * z0 + d1 * __shfl_xor_sync(FM, z0, 1)
             + d2 * __shfl_xor_sync(FM, z0, 2) + d3 * __shfl_xor_sync(FM, z0, 3);
    float w1 = d0 * z1 + d1 * __shfl_xor_sync(FM, z1, 1)
             + d2 * __shfl_xor_sync(FM, z1, 2) + d3 * __shfl_xor_sync(FM, z1, 3);
    float w2 = d0 * z2 + d1 * __shfl_xor_sync(FM, z2, 1)
             + d2 * __shfl_xor_sync(FM, z2, 2) + d3 * __shfl_xor_sync(FM, z2, 3);
    float w3 = d0 * z3 + d1 * __shfl_xor_sync(FM, z3, 1)
             + d2 * __shfl_xor_sync(FM, z3, 2) + d3 * __shfl_xor_sync(FM, z3, 3);

    // RIGHT stage B: ga-mix (col bits 2,3 of lane) -> masks 4,8,12
    const int ga = c >> 2;
    const float g0 = U1[ga * 4 + ga];
    const float g1 = U1[ga * 4 + (ga ^ 1)];
    const float g2 = U1[ga * 4 + (ga ^ 2)];
    const float g3 = U1[ga * 4 + (ga ^ 3)];
    float o0 = g0 * w0 + g1 * __shfl_xor_sync(FM, w0, 4)
             + g2 * __shfl_xor_sync(FM, w0, 8) + g3 * __shfl_xor_sync(FM, w0, 12);
    float o1 = g0 * w1 + g1 * __shfl_xor_sync(FM, w1, 4)
             + g2 * __shfl_xor_sync(FM, w1, 8) + g3 * __shfl_xor_sync(FM, w1, 12);
    float o2 = g0 * w2 + g1 * __shfl_xor_sync(FM, w2, 4)
             + g2 * __shfl_xor_sync(FM, w2, 8) + g3 * __shfl_xor_sync(FM, w2, 12);
    float o3 = g0 * w3 + g1 * __shfl_xor_sync(FM, w3, 4)
             + g2 * __shfl_xor_sync(FM, w3, 8) + g3 * __shfl_xor_sync(FM, w3, 12);

    // direct store: coalesced (same pattern as load)
    {
        float* po = out + growb * NP + gcol;
        po[0]      = o0;
        po[NP]     = o1;
        po[2 * NP] = o2;
        po[3 * NP] = o3;
    }

    if (mirror) {
        // smem transpose: sT[c][4rg..4rg+3] = o (float4 STS)
        *reinterpret_cast<float4*>(&sT[c][4 * rg]) = make_float4(o0, o1, o2, o3);
        __syncthreads();
        // mirror-store mapping: k = tid&3 (lane), cR = tid>>2
        const int k2 = tid & 3, cR = tid >> 2;
        const int mrow = pair_idx(4 * t1 + (cR >> 2), 4 * t2 + (cR & 3));
        float* pm = out + mrow * NP + pair_idx(4 * T1, 4 * T2) + k2;
        // columns growb2(j) + k2 for j = 0..3; growb2(j) = pair_idx(4T1+j, 4T2)
        #pragma unroll
        for (int j = 0; j < 4; j++) {
            const int gb = pair_idx(4 * T1 + j, 4 * T2);
            out[mrow * NP + gb + k2] = sT[cR][4 * j + k2];
        }
        (void)pm;
    }
}

// ---- J diagonal (DI x 6): smem 3-stage with precomputed W (from R13) -------
template <int DI>
__device__ __forceinline__ void path_jdiag(
    const float* __restrict__ rho, float* __restrict__ out,
    const float* __restrict__ thetas,
    int T1, int T2, int t1, int tid, bool mirror,
    float (*sVw)[32], float (*sW)[36], float (*bA)[9], float (*bB)[9])
{
    const int w = tid >> 5, lane = tid & 31;

    float rs[2];
    #pragma unroll
    for (int k = 0; k < 2; k++) {
        int e = tid + 64 * k;
        if (e < DI * 6)
            rs[k] = __ldg(rho + gidx<DI>(T1, T2, e / 6) * NP + gidx<6>(t1, t1, e % 6));
    }
    float* sV = sVw[w];
    compose_V_warp(lane, thetas, sV);
    __syncwarp();

    #pragma unroll
    for (int k = 0; k < 2; k++) {
        int e = tid + 64 * k;
        if (e < 72) {
            int side = e / 36, mn = e % 36, mm = mn / 6, nn = mn % 6;
            const float* U = sVw[w] + side * 16;
            int a = p1of(mm), b = p2of(mm), gg = p1of(nn), d = p2of(nn);
            sW[side][mn] = U[a * 4 + gg] * U[b * 4 + d] - U[a * 4 + d] * U[b * 4 + gg];
        }
    }
    #pragma unroll
    for (int k = 0; k < 2; k++) {
        int e = tid + 64 * k;
        if (e < DI * 6) bA[e / 6][e % 6] = rs[k];
    }
    __syncthreads();

    const float* V1 = sVw[w] + (T1 >> 2) * 16;
    const float* V2 = sVw[w] + (T2 >> 2) * 16;
    const float* WI = sW[T1 >> 2];
    #pragma unroll
    for (int k = 0; k < 2; k++) {
        int e = tid + 64 * k;
        if (e < DI * 6) {
            int mm = e / 6, c = e % 6;
            float acc = 0.f;
            if (DI == 16) {
                const int al = mm >> 2, be = mm & 3;
                #pragma unroll
                for (int ap = 0; ap < 4; ap++) {
                    float s2 = 0.f;
                    #pragma unroll
                    for (int bp = 0; bp < 4; bp++)
                        s2 += V2[be * 4 + bp] * bA[ap * 4 + bp][c];
                    acc += V1[al * 4 + ap] * s2;
                }
            } else {
                #pragma unroll
                for (int n = 0; n < 6; n++)
                    acc += WI[mm * 6 + n] * bA[n][c];
            }
            bB[mm][c] = acc;
        }
    }
    __syncthreads();

    const float* WJ = sW[t1 >> 2];
    #pragma unroll
    for (int k = 0; k < 2; k++) {
        int e = tid + 64 * k;
        if (e < DI * 6) {
            int mm = e / 6, c = e % 6;
            float acc = 0.f;
            #pragma unroll
            for (int n = 0; n < 6; n++)
                acc += WJ[c * 6 + n] * bB[mm][n];
            const int gr = gidx<DI>(T1, T2, mm);
            const int gc = gidx<6>(t1, t1, c);
            out[gr * NP + gc] = acc;
            if (mirror) out[gc * NP + gr] = acc;
        }
    }
}

__global__ void __launch_bounds__(64, 16)
rbs_kernel(const float* __restrict__ rho, float* __restrict__ out,
           const float* __restrict__ thetas)
{
    __shared__ __align__(16) float sVw[2][32];
    __shared__ __align__(16) float4 sY[64];
    __shared__ __align__(16) float sT[16][20];
    __shared__ float sW[2][36];
    __shared__ float bA[16][9], bB[16][9];

    const int tid = threadIdx.x;

    // decode upper-triangular pair (I <= J)
    const int k = blockIdx.x;
    int I = (int)((73.0f - sqrtf(5329.0f - 8.0f * (float)k)) * 0.5f);
    while (tri_base(I + 1) <= k) ++I;
    while (tri_base(I) > k) --I;
    const int J = I + (k - tri_base(I));
    const bool mirror = (I != J);

    int T1, T2, DI, t1, t2, DJ;
    decode_block(I, T1, T2, DI);
    decode_block(J, t1, t2, DJ);

    if (DJ == 16) {
        // I <= J and J cross => I cross too
        path_cross16(rho, out, thetas, T1, T2, t1, t2, tid, mirror, sVw, sY, sT);
    } else if (DI == 16) {
        path_jdiag<16>(rho, out, thetas, T1, T2, t1, tid, mirror, sVw, sW, bA, bB);
    } else {
        path_jdiag< 6>(rho, out, thetas, T1, T2, t1, tid, mirror, sVw, sW, bA, bB);
    }
}

extern "C" void kernel_launch(void* const* d_in, const int* in_sizes, int n_in,
                              void* d_out, int out_size) {
    // metadata order: rho, thetas, A_stack, B_stack, C_stack, u_idx, p_idx
    const float* rho    = (const float*)d_in[0];
    const float* thetas = (const float*)d_in[1];
    float* out = (float*)d_out;

    rbs_kernel<<<666, 64>>>(rho, out, thetas);
}

// round 15
// speedup vs baseline: 1.0435x; 1.0435x over previous
#include <cuda_runtime.h>

// out = M rho M^T on the Hamming-weight-2 basis (N = C(32,2) = 496).
// M block-diagonal over 36 pair-blocks; TWO distinct 4x4 tile matrices
// (V_row: params 0-5, V_col: params 6-11), pyramid order {0,1,0,2,1,0}.
//   cross block (t1<t2): dim 16, B = V_t1 (x) V_t2
//   diag  block (t):     dim 6,  B = Lambda^2(V_t) = W
// SYMMETRY: compute only I <= J (666 CTAs), mirror out[J,I] = out[I,J]^T.
// R13 structure + __sincosf (fast intrinsic) instead of precise sincosf.

#define NP 496
#define FM 0xFFFFFFFFu

__device__ __forceinline__ int pair_idx(int a, int b) {
    return a * 31 - (a * (a - 1)) / 2 + (b - a - 1);
}

__device__ __forceinline__ void decode_block(int B, int& t1, int& t2, int& dim) {
    if (B < 28) {
        int rem = B, a = 0;
        while (rem >= 7 - a) { rem -= 7 - a; a++; }
        t1 = a; t2 = a + 1 + rem; dim = 16;
    } else {
        t1 = B - 28; t2 = t1; dim = 6;
    }
}

__device__ __forceinline__ int tri_base(int I) { return (73 * I - I * I) >> 1; }

// P1 = {0,0,0,1,1,2}, P2 = {1,2,3,2,3,3}, 3 bits/entry
#define P1W 0x11200
#define P2W 0x1B4D1
__device__ __forceinline__ int p1of(int m) { return (P1W >> (3 * m)) & 7; }
__device__ __forceinline__ int p2of(int m) { return (P2W >> (3 * m)) & 7; }

template <int D>
__device__ __forceinline__ int gidx(int t1, int t2, int m) {
    if (D == 16) return pair_idx(4 * t1 + (m >> 2), 4 * t2 + (m & 3));
    return pair_idx(4 * t1 + p1of(m), 4 * t1 + p2of(m));
}

// One warp composes BOTH tile matrices: half-warp h builds group h.
// Lane h*16+idx ends holding V[h][idx]; written to warp-private sVw[32].
__device__ __forceinline__ void compose_V_warp(int lane, const float* __restrict__ thetas,
                                               float* sVw) {
    const int h = lane >> 4, idx = lane & 15;
    float s, c;
    __sincosf(__ldg(thetas + h * 6 + (idx % 6)), &s, &c);   // fast MUFU path
    const int r = idx >> 2;
    float v = ((idx >> 2) == (idx & 3)) ? 1.f : 0.f;
    const int jseq[6] = {0, 1, 0, 2, 1, 0};
    #pragma unroll
    for (int gi = 0; gi < 6; gi++) {
        const int j = jseq[gi];
        const int src = (lane & 16) + gi;
        float cg = __shfl_sync(FM, c, src);
        float sg = __shfl_sync(FM, s, src);
        float vu = __shfl_sync(FM, v, (lane + 4) & 31);
        float vd = __shfl_sync(FM, v, (lane - 4) & 31);
        if (r == j)          v = cg * v + sg * vu;
        else if (r == j + 1) v = cg * v - sg * vd;
    }
    sVw[lane] = v;
}

__device__ __forceinline__ float4 shflx4(float4 a, int m) {
    float4 r;
    r.x = __shfl_xor_sync(FM, a.x, m);
    r.y = __shfl_xor_sync(FM, a.y, m);
    r.z = __shfl_xor_sync(FM, a.z, m);
    r.w = __shfl_xor_sync(FM, a.w, m);
    return r;
}
__device__ __forceinline__ float4 f4fma(float4 acc, float w, float4 x) {
    acc.x += w * x.x; acc.y += w * x.y; acc.z += w * x.z; acc.w += w * x.w;
    return acc;
}
__device__ __forceinline__ float4 f4mul(float w, float4 x) {
    return make_float4(w * x.x, w * x.y, w * x.z, w * x.w);
}

// ---- cross x cross (16x16): 2 warps, registers + butterflies + 1 exchange --
__device__ __forceinline__ void path_cross16(
    const float* __restrict__ rho, float* __restrict__ out,
    const float* __restrict__ thetas,
    int T1, int T2, int t1, int t2, int tid, bool mirror,
    float (*sVw)[32], float4* sY)
{
    const int w = tid >> 5, lane = tid & 31;
    const int m = tid >> 2, g = tid & 3;      // row m (0..15), col group g
    const int al = m >> 2;                    // lane bit4 = al&1, warp = al>>1
    const int be = m & 3;                     // lane bits 2,3

    const int grow = gidx<16>(T1, T2, m);
    const int colbase = pair_idx(4 * t1 + g, 4 * t2);

    // early gather (4 consecutive floats of row grow)
    float4 x;
    {
        const float* p = rho + grow * NP + colbase;
        x.x = __ldg(p); x.y = __ldg(p + 1); x.z = __ldg(p + 2); x.w = __ldg(p + 3);
    }
    float* sV = sVw[w];
    compose_V_warp(lane, thetas, sV);         // overlaps gather; warp-private
    __syncwarp();

    const float* V1 = sV + (T1 >> 2) * 16;
    const float* V2 = sV + (T2 >> 2) * 16;
    const float* U1 = sV + (t1 >> 2) * 16;
    const float* U2 = sV + (t2 >> 2) * 16;

    // LEFT stage 1 (be-mix, within warp; be = lane bits 2,3 -> masks 4,8,12)
    float4 y = f4mul(V2[be * 4 + be], x);
    y = f4fma(y, V2[be * 4 + (be ^ 1)], shflx4(x, 4));
    y = f4fma(y, V2[be * 4 + (be ^ 2)], shflx4(x, 8));
    y = f4fma(y, V2[be * 4 + (be ^ 3)], shflx4(x, 12));

    // al^1 partner within warp (lane bit4)
    float4 y1 = shflx4(y, 16);

    // exchange with other warp for al^2, al^3
    sY[tid] = y;
    __syncthreads();
    float4 y2 = sY[(1 - w) * 32 + lane];
    float4 y3 = sY[(1 - w) * 32 + (lane ^ 16)];

    // LEFT stage 2 (al-mix)
    float4 z = f4mul(V1[al * 4 + al], y);
    z = f4fma(z, V1[al * 4 + (al ^ 1)], y1);
    z = f4fma(z, V1[al * 4 + (al ^ 2)], y2);
    z = f4fma(z, V1[al * 4 + (al ^ 3)], y3);

    // RIGHT stage A (de-mix, local within float4; U2 row-major [de'][de])
    float4 w4;
    w4.x = U2[0]  * z.x + U2[1]  * z.y + U2[2]  * z.z + U2[3]  * z.w;
    w4.y = U2[4]  * z.x + U2[5]  * z.y + U2[6]  * z.z + U2[7]  * z.w;
    w4.z = U2[8]  * z.x + U2[9]  * z.y + U2[10] * z.z + U2[11] * z.w;
    w4.w = U2[12] * z.x + U2[13] * z.y + U2[14] * z.z + U2[15] * z.w;

    // RIGHT stage B (ga-mix; g = lane bits 0,1 -> masks 1,2,3)
    float4 o = f4mul(U1[g * 4 + g], w4);
    o = f4fma(o, U1[g * 4 + (g ^ 1)], shflx4(w4, 1));
    o = f4fma(o, U1[g * 4 + (g ^ 2)], shflx4(w4, 2));
    o = f4fma(o, U1[g * 4 + (g ^ 3)], shflx4(w4, 3));

    // store (+ transposed mirror)
    {
        float* p = out + grow * NP + colbase;
        p[0] = o.x; p[1] = o.y; p[2] = o.z; p[3] = o.w;
    }
    if (mirror) {
        out[(colbase + 0) * NP + grow] = o.x;
        out[(colbase + 1) * NP + grow] = o.y;
        out[(colbase + 2) * NP + grow] = o.z;
        out[(colbase + 3) * NP + grow] = o.w;
    }
}

// ---- J diagonal (DI x 6): smem 3-stage with precomputed W ------------------
template <int DI>
__device__ __forceinline__ void path_jdiag(
    const float* __restrict__ rho, float* __restrict__ out,
    const float* __restrict__ thetas,
    int T1, int T2, int t1, int tid, bool mirror,
    float (*sVw)[32], float (*sW)[36], float (*bA)[9], float (*bB)[9])
{
    const int w = tid >> 5, lane = tid & 31;

    float rs[2];
    #pragma unroll
    for (int k = 0; k < 2; k++) {
        int e = tid + 64 * k;
        if (e < DI * 6)
            rs[k] = __ldg(rho + gidx<DI>(T1, T2, e / 6) * NP + gidx<6>(t1, t1, e % 6));
    }
    float* sV = sVw[w];
    compose_V_warp(lane, thetas, sV);
    __syncwarp();

    // precompute W = Lambda^2(V) for both groups (72 entries over 64 threads)
    #pragma unroll
    for (int k = 0; k < 2; k++) {
        int e = tid + 64 * k;
        if (e < 72) {
            int side = e / 36, mn = e % 36, mm = mn / 6, nn = mn % 6;
            const float* U = sVw[w] + side * 16;
            int a = p1of(mm), b = p2of(mm), gg = p1of(nn), d = p2of(nn);
            sW[side][mn] = U[a * 4 + gg] * U[b * 4 + d] - U[a * 4 + d] * U[b * 4 + gg];
        }
    }
    #pragma unroll
    for (int k = 0; k < 2; k++) {
        int e = tid + 64 * k;
        if (e < DI * 6) bA[e / 6][e % 6] = rs[k];
    }
    __syncthreads();

    const float* V1 = sVw[w] + (T1 >> 2) * 16;
    const float* V2 = sVw[w] + (T2 >> 2) * 16;
    const float* WI = sW[T1 >> 2];
    #pragma unroll
    for (int k = 0; k < 2; k++) {
        int e = tid + 64 * k;
        if (e < DI * 6) {
            int mm = e / 6, c = e % 6;
            float acc = 0.f;
            if (DI == 16) {
                const int al = mm >> 2, be = mm & 3;
                #pragma unroll
                for (int ap = 0; ap < 4; ap++) {
                    float s2 = 0.f;
                    #pragma unroll
                    for (int bp = 0; bp < 4; bp++)
                        s2 += V2[be * 4 + bp] * bA[ap * 4 + bp][c];
                    acc += V1[al * 4 + ap] * s2;
                }
            } else {
                #pragma unroll
                for (int n = 0; n < 6; n++)
                    acc += WI[mm * 6 + n] * bA[n][c];
            }
            bB[mm][c] = acc;
        }
    }
    __syncthreads();

    const float* WJ = sW[t1 >> 2];
    #pragma unroll
    for (int k = 0; k < 2; k++) {
        int e = tid + 64 * k;
        if (e < DI * 6) {
            int mm = e / 6, c = e % 6;
            float acc = 0.f;
            #pragma unroll
            for (int n = 0; n < 6; n++)
                acc += WJ[c * 6 + n] * bB[mm][n];
            const int gr = gidx<DI>(T1, T2, mm);
            const int gc = gidx<6>(t1, t1, c);
            out[gr * NP + gc] = acc;
            if (mirror) out[gc * NP + gr] = acc;
        }
    }
}

__global__ void __launch_bounds__(64, 16)
rbs_kernel(const float* __restrict__ rho, float* __restrict__ out,
           const float* __restrict__ thetas)
{
    __shared__ __align__(16) float sVw[2][32];
    __shared__ __align__(16) float4 sY[64];
    __shared__ float sW[2][36];
    __shared__ float bA[16][9], bB[16][9];

    const int tid = threadIdx.x;

    // decode upper-triangular pair (I <= J)
    const int k = blockIdx.x;
    int I = (int)((73.0f - sqrtf(5329.0f - 8.0f * (float)k)) * 0.5f);
    while (tri_base(I + 1) <= k) ++I;
    while (tri_base(I) > k) --I;
    const int J = I + (k - tri_base(I));
    const bool mirror = (I != J);

    int T1, T2, DI, t1, t2, DJ;
    decode_block(I, T1, T2, DI);
    decode_block(J, t1, t2, DJ);

    if (DJ == 16) {
        // I <= J and J cross => I cross too
        path_cross16(rho, out, thetas, T1, T2, t1, t2, tid, mirror, sVw, sY);
    } else if (DI == 16) {
        path_jdiag<16>(rho, out, thetas, T1, T2, t1, tid, mirror, sVw, sW, bA, bB);
    } else {
        path_jdiag< 6>(rho, out, thetas, T1, T2, t1, tid, mirror, sVw, sW, bA, bB);
    }
}

extern "C" void kernel_launch(void* const* d_in, const int* in_sizes, int n_in,
                              void* d_out, int out_size) {
    // metadata order: rho, thetas, A_stack, B_stack, C_stack, u_idx, p_idx
    const float* rho    = (const float*)d_in[0];
    const float* thetas = (const float*)d_in[1];
    float* out = (float*)d_out;

    rbs_kernel<<<666, 64>>>(rho, out, thetas);
}